// round 5
// baseline (speedup 1.0000x reference)
#include <cuda_runtime.h>
#include <stdint.h>

#define NB      16
#define NCLS    80
#define NANCH   17064
#define TOPK    1000
#define NBUCK   2048
#define CANDCAP 4096

// ---------------- scratch (static device globals; no allocation) ----------------
__device__ float              d_score[NB * NANCH];
__device__ int                d_cls  [NB * NANCH];
__device__ float4             d_box  [NB * NANCH];
__device__ int                d_hist [NB * NBUCK];
__device__ int                d_cut  [NB];
__device__ int                d_cnt  [NB];
__device__ unsigned long long d_cand [NB * CANDCAP];
__device__ float              d_tscore[NB * TOPK];
__device__ int                d_tcls  [NB * TOPK];
__device__ float4             d_tbox  [NB * TOPK];

struct Ptrs {
    const float* cls[5];
    const float* ctr[5];
    const float* reg[5];
};

// ---------------- XLA:CPU vectorized exp (__xla_cpu_runtime_ExpVxF32) ----------------
// Cephes/Eigen pexp clone as emitted by GenerateVF32Exp:
//   clamp [-88.3762626647949, 88.3762626647950]
//   fx = floor(fmuladd(x, log2e, 0.5))        (fmuladd -> fused on aarch64)
//   tmp = fx*C1; z = fx*C2; x -= tmp; x -= z  (separate mul/sub, NOT fma)
//   Horner p0..p5 with fmuladd; y = fmuladd(y, x*x, x) + 1
//   scale by 2^n via (n+127)<<23
__device__ __forceinline__ float xla_cpu_expf(float x) {
    x = fminf(x,  88.3762626647950f);
    x = fmaxf(x, -88.3762626647949f);
    float fx = floorf(fmaf(x, 1.44269504088896341f, 0.5f));
    float tmp = __fmul_rn(fx, 0.693359375f);
    float z   = __fmul_rn(fx, -2.12194440e-4f);
    x = __fsub_rn(x, tmp);
    x = __fsub_rn(x, z);
    z = __fmul_rn(x, x);
    float y = 1.9875691500e-4f;
    y = fmaf(y, x, 1.3981999507e-3f);
    y = fmaf(y, x, 8.3334519073e-3f);
    y = fmaf(y, x, 4.1665795894e-2f);
    y = fmaf(y, x, 1.6666665459e-1f);
    y = fmaf(y, x, 5.0000001201e-1f);
    y = fmaf(y, z, x);
    y = __fadd_rn(y, 1.0f);
    int n = (int)fx;
    float p2n = __int_as_float((n + 127) << 23);
    return __fmul_rn(y, p2n);
}

// XLA logistic_expander: 1 / (1 + exp(-x))
__device__ __forceinline__ float xla_sigmoid(float x) {
    float e = xla_cpu_expf(-x);
    return __fdiv_rn(1.0f, __fadd_rn(1.0f, e));
}

// ---------------- kernel 0: zero histograms / counters ----------------
__global__ void init_kernel() {
    int i = blockIdx.x * blockDim.x + threadIdx.x;
    if (i < NB * NBUCK) d_hist[i] = 0;
    if (i < NB)         d_cnt[i]  = 0;
}

// ---------------- kernel 1: scores, classes, boxes, histogram ----------------
__global__ void score_kernel(Ptrs P) {
    __shared__ int shist[NBUCK];
    int b = blockIdx.y;
    for (int i = threadIdx.x; i < NBUCK; i += blockDim.x) shist[i] = 0;
    __syncthreads();

    int a = blockIdx.x * blockDim.x + threadIdx.x;
    if (a < NANCH) {
        int lvl, off, hw, W, stride;
        if      (a < 12800) { lvl = 0; off = 0;     hw = 12800; W = 128; stride = 8;   }
        else if (a < 16000) { lvl = 1; off = 12800; hw = 3200;  W = 64;  stride = 16;  }
        else if (a < 16800) { lvl = 2; off = 16000; hw = 800;   W = 32;  stride = 32;  }
        else if (a < 17008) { lvl = 3; off = 16800; hw = 208;   W = 16;  stride = 64;  }
        else                { lvl = 4; off = 17008; hw = 56;    W = 8;   stride = 128; }
        int pix = a - off;
        int y = pix / W;
        int x = pix - y * W;
        float cx = (float)(x * stride + stride / 2);
        float cy = (float)(y * stride + stride / 2);

        const float* cp = P.cls[lvl] + (size_t)b * NCLS * hw + pix;
        float best = -1.0f; int bi = 0;
        #pragma unroll 4
        for (int c = 0; c < NCLS; c++) {
            float s = xla_sigmoid(cp[(size_t)c * hw]);
            if (s > best) { best = s; bi = c; }   // strict > : first-occurrence argmax
        }
        float ctr = xla_sigmoid(P.ctr[lvl][(size_t)b * hw + pix]);
        float sc  = __fmul_rn(best, ctr);

        const float* rp = P.reg[lvl] + (size_t)b * 4 * hw + pix;
        float r0 = rp[0];
        float r1 = rp[(size_t)hw];
        float r2 = rp[(size_t)2 * hw];
        float r3 = rp[(size_t)3 * hw];
        float4 bx;
        bx.x = __fsub_rn(cx, r0);
        bx.y = __fsub_rn(cy, r1);
        bx.z = __fadd_rn(cx, r2);
        bx.w = __fadd_rn(cy, r3);

        int idx = b * NANCH + a;
        d_score[idx] = sc;
        d_cls[idx]   = bi + 1;
        d_box[idx]   = bx;

        int bu = (int)(sc * 2048.0f);
        bu = bu < 0 ? 0 : (bu > 2047 ? 2047 : bu);
        atomicAdd(&shist[bu], 1);
    }
    __syncthreads();
    for (int i = threadIdx.x; i < NBUCK; i += blockDim.x) {
        int v = shist[i];
        if (v) atomicAdd(&d_hist[b * NBUCK + i], v);
    }
}

// ---------------- kernel 2: find cutoff bucket (rank-1000) ----------------
__global__ void cutoff_kernel() {
    int b = blockIdx.x;
    __shared__ int csum[64];
    int t = threadIdx.x;   // block = 64
    int s = 0;
    for (int k = 0; k < 32; k++) {
        int bin = 2047 - (t * 32 + k);
        s += d_hist[b * NBUCK + bin];
    }
    csum[t] = s;
    __syncthreads();
    if (t == 0) {
        int cum = 0, cut = 0;
        for (int ch = 0; ch < 64; ch++) {
            if (cum + csum[ch] >= TOPK) {
                for (int k = 0; k < 32; k++) {
                    int bin = 2047 - (ch * 32 + k);
                    cum += d_hist[b * NBUCK + bin];
                    if (cum >= TOPK) { cut = bin; break; }
                }
                break;
            }
            cum += csum[ch];
        }
        d_cut[b] = cut;
    }
}

// ---------------- kernel 3: compact candidates ----------------
__global__ void compact_kernel() {
    int b = blockIdx.y;
    int a = blockIdx.x * blockDim.x + threadIdx.x;
    if (a >= NANCH) return;
    float sc = d_score[b * NANCH + a];
    int bu = (int)(sc * 2048.0f);
    bu = bu < 0 ? 0 : (bu > 2047 ? 2047 : bu);
    if (bu >= d_cut[b]) {
        int pos = atomicAdd(&d_cnt[b], 1);
        if (pos < CANDCAP) {
            unsigned long long key =
                ((unsigned long long)__float_as_uint(sc) << 32) |
                (unsigned)(~(unsigned)a);   // ties: smaller index -> larger low word -> first
            d_cand[b * CANDCAP + pos] = key;
        }
    }
}

// ---------------- kernel 4: per-batch bitonic sort + top-1000 gather ----------------
__global__ void sort_kernel() {
    __shared__ unsigned long long keys[CANDCAP];
    int b = blockIdx.x;
    int tid = threadIdx.x;  // block = 1024
    int cnt = d_cnt[b];
    if (cnt > CANDCAP) cnt = CANDCAP;
    for (int i = tid; i < CANDCAP; i += 1024)
        keys[i] = (i < cnt) ? d_cand[b * CANDCAP + i] : 0ULL;
    __syncthreads();

    for (int k = 2; k <= CANDCAP; k <<= 1) {
        for (int j = k >> 1; j > 0; j >>= 1) {
            for (int i = tid; i < CANDCAP; i += 1024) {
                int ixj = i ^ j;
                if (ixj > i) {
                    unsigned long long A = keys[i], Bk = keys[ixj];
                    bool desc = ((i & k) == 0);
                    bool sw = desc ? (A < Bk) : (A > Bk);
                    if (sw) { keys[i] = Bk; keys[ixj] = A; }
                }
            }
            __syncthreads();
        }
    }
    if (tid < TOPK) {
        unsigned long long key = keys[tid];
        float sc = __uint_as_float((unsigned)(key >> 32));
        int a = (int)(~(unsigned)(key & 0xFFFFFFFFu));
        int src = b * NANCH + a;
        int dst = b * TOPK + tid;
        d_tscore[dst] = sc;
        d_tcls[dst]   = d_cls[src];
        d_tbox[dst]   = d_box[src];
    }
}

// ---------------- kernel 5: NMS (bitmask + sparse sweep) + outputs ----------------
__global__ void nms_kernel(float* __restrict__ out) {
    extern __shared__ char smem_raw[];
    float4*   sbox   = (float4*)(smem_raw);                 // 16000 B
    float*    sarea  = (float*)(smem_raw + 16000);          //  4000 B
    float*    sscore = (float*)(smem_raw + 20000);          //  4000 B
    int*      scls   = (int*)(smem_raw + 24000);            //  4000 B
    unsigned* mask   = (unsigned*)(smem_raw + 28000);       // 128000 B
    unsigned* rowAny = (unsigned*)(smem_raw + 156032);      // 128 B
    unsigned* remw   = (unsigned*)(smem_raw + 156160);      // 128 B
    float*    sred   = (float*)(smem_raw + 156288);         // 128 B

    int b = blockIdx.x;
    int tid = threadIdx.x;           // block = 1024
    int lane = tid & 31;
    int w = tid >> 5;

    for (int i = tid; i < TOPK; i += 1024) {
        sbox[i]   = d_tbox[b * TOPK + i];
        sscore[i] = d_tscore[b * TOPK + i];
        scls[i]   = d_tcls[b * TOPK + i];
    }
    for (int i = tid; i < TOPK * 32; i += 1024) mask[i] = 0;
    if (tid < 32) rowAny[tid] = 0;
    __syncthreads();

    // max over all topk box coords
    float m = -3.0e38f;
    for (int i = tid; i < TOPK; i += 1024) {
        float4 bx = sbox[i];
        m = fmaxf(m, fmaxf(fmaxf(bx.x, bx.y), fmaxf(bx.z, bx.w)));
    }
    for (int o = 16; o; o >>= 1) m = fmaxf(m, __shfl_xor_sync(0xffffffffu, m, o));
    if (lane == 0) sred[w] = m;
    __syncthreads();
    if (w == 0) {
        float mm = sred[lane];
        for (int o = 16; o; o >>= 1) mm = fmaxf(mm, __shfl_xor_sync(0xffffffffu, mm, o));
        if (lane == 0) sred[0] = mm;
    }
    __syncthreads();
    float M1 = __fadd_rn(sred[0], 1.0f);

    // class-offset boxes + areas
    for (int i = tid; i < TOPK; i += 1024) {
        float off = __fmul_rn((float)scls[i], M1);
        float4 bx = sbox[i];
        bx.x = __fadd_rn(bx.x, off);
        bx.y = __fadd_rn(bx.y, off);
        bx.z = __fadd_rn(bx.z, off);
        bx.w = __fadd_rn(bx.w, off);
        sbox[i] = bx;
        sarea[i] = __fmul_rn(__fadd_rn(__fsub_rn(bx.z, bx.x), 1.0f),
                             __fadd_rn(__fsub_rn(bx.w, bx.y), 1.0f));
    }
    __syncthreads();

    // suppression bitmask: warp per row, ballot per 32-j word
    for (int i = w; i < TOPK; i += 32) {
        float4 bi = sbox[i];
        float ai = sarea[i];
        unsigned any = 0;
        for (int wd = i >> 5; wd < 32; wd++) {
            int j = wd * 32 + lane;
            bool pred = false;
            if (j < TOPK && j > i) {
                float4 bj = sbox[j];
                float xmin = fmaxf(bi.x, bj.x);
                float ymin = fmaxf(bi.y, bj.y);
                float xmax = fminf(bi.z, bj.z);
                float ymax = fminf(bi.w, bj.w);
                float iw = fmaxf(__fsub_rn(xmax, xmin), 0.0f);
                float ih = fmaxf(__fsub_rn(ymax, ymin), 0.0f);
                float inter = __fmul_rn(iw, ih);
                float den = __fsub_rn(__fadd_rn(ai, sarea[j]), inter);
                pred = __fdiv_rn(inter, den) > 0.6f;
            }
            unsigned bal = __ballot_sync(0xffffffffu, pred);
            if (lane == 0) mask[i * 32 + wd] = bal;
            any |= bal;
        }
        if (lane == 0 && any) atomicOr(&rowAny[i >> 5], 1u << (i & 31));
    }
    __syncthreads();

    // initial removed = !valid
    {
        bool invalid = (tid >= TOPK) || (sscore[tid] < 0.05f);
        unsigned bal = __ballot_sync(0xffffffffu, invalid);
        if (lane == 0) remw[w] = bal;
    }
    __syncthreads();

    // sequential greedy sweep, single warp, sparse rows only
    if (w == 0) {
        unsigned rem = remw[lane];
        for (int c = 0; c < 32; c++) {
            unsigned bits = rowAny[c];
            while (bits) {
                int bpos = __ffs(bits) - 1;
                bits &= bits - 1;
                int i = c * 32 + bpos;
                unsigned wi = __shfl_sync(0xffffffffu, rem, c);
                if (!((wi >> bpos) & 1u)) rem |= mask[i * 32 + lane];
            }
        }
        remw[lane] = rem;
    }
    __syncthreads();

    // outputs: scores | classes | boxes (float32, concatenated)
    float* out_sc = out;
    float* out_cl = out + NB * TOPK;
    float* out_bx = out + 2 * NB * TOPK;
    for (int i = tid; i < TOPK; i += 1024) {
        bool kp = !((remw[i >> 5] >> (i & 31)) & 1u);
        out_sc[b * TOPK + i] = kp ? sscore[i] : 0.0f;
        out_cl[b * TOPK + i] = kp ? (float)scls[i] : 0.0f;
        float4 ob = d_tbox[b * TOPK + i];
        float4 r;
        r.x = kp ? ob.x : 0.0f;
        r.y = kp ? ob.y : 0.0f;
        r.z = kp ? ob.z : 0.0f;
        r.w = kp ? ob.w : 0.0f;
        ((float4*)out_bx)[b * TOPK + i] = r;
    }
}

// ---------------- host ----------------
extern "C" void kernel_launch(void* const* d_in, const int* in_sizes, int n_in,
                              void* d_out, int out_size) {
    Ptrs P;
    if (n_in >= 15 && in_sizes[1] == 4096000) {
        for (int i = 0; i < 5; i++) {
            P.cls[i] = (const float*)d_in[i];
            P.ctr[i] = (const float*)d_in[5 + i];
            P.reg[i] = (const float*)d_in[10 + i];
        }
    } else {
        for (int i = 0; i < 5; i++) {
            P.cls[i] = (const float*)d_in[3 * i];
            P.ctr[i] = (const float*)d_in[3 * i + 1];
            P.reg[i] = (const float*)d_in[3 * i + 2];
        }
    }

    static bool attr_set = false;
    if (!attr_set) {
        cudaFuncSetAttribute(nms_kernel, cudaFuncAttributeMaxDynamicSharedMemorySize, 156416);
        attr_set = true;
    }

    init_kernel<<<(NB * NBUCK + 255) / 256, 256>>>();
    dim3 g2((NANCH + 255) / 256, NB);
    score_kernel<<<g2, 256>>>(P);
    cutoff_kernel<<<NB, 64>>>();
    compact_kernel<<<g2, 256>>>();
    sort_kernel<<<NB, 1024>>>();
    nms_kernel<<<NB, 1024, 156416>>>((float*)d_out);
}

// round 6
// speedup vs baseline: 2.7054x; 2.7054x over previous
#include <cuda_runtime.h>
#include <stdint.h>

#define NB      16
#define NCLS    80
#define NANCH   17064
#define TOPK    1000
#define NBUCK   2048
#define CANDCAP 4096

// ---------------- scratch (static device globals; no allocation) ----------------
__device__ float              d_score[NB * NANCH];
__device__ int                d_cls  [NB * NANCH];
__device__ float4             d_box  [NB * NANCH];
__device__ int                d_hist [NB * NBUCK];
__device__ int                d_cut  [NB];
__device__ int                d_cnt  [NB];
__device__ unsigned long long d_cand [NB * CANDCAP];
__device__ float              d_tscore[NB * TOPK];
__device__ int                d_tcls  [NB * TOPK];
__device__ float4             d_tbox  [NB * TOPK];
__device__ float4             d_nbox  [NB * TOPK];   // class-offset boxes
__device__ float              d_narea [NB * TOPK];   // areas of offset boxes
__device__ unsigned           d_mask  [NB * TOPK * 32];
__device__ unsigned           d_rowany[NB * 32];

struct Ptrs {
    const float* cls[5];
    const float* ctr[5];
    const float* reg[5];
};

// midpoint between 0.6f and nextafterf(0.6f): exact 25-bit value.
// __fdiv_rn(inter,den) > 0.6f  <=>  inter/den (real) > MID  <=>  (double)inter > MID*(double)den (exact)
#define IOU_MID 0.6000000536441802978515625

// ---------------- XLA:CPU vectorized exp (Cephes clone, bit-exact vs reference) ----------------
__device__ __forceinline__ float xla_cpu_expf(float x) {
    x = fminf(x,  88.3762626647950f);
    x = fmaxf(x, -88.3762626647949f);
    float fx = floorf(fmaf(x, 1.44269504088896341f, 0.5f));
    float tmp = __fmul_rn(fx, 0.693359375f);
    float z   = __fmul_rn(fx, -2.12194440e-4f);
    x = __fsub_rn(x, tmp);
    x = __fsub_rn(x, z);
    z = __fmul_rn(x, x);
    float y = 1.9875691500e-4f;
    y = fmaf(y, x, 1.3981999507e-3f);
    y = fmaf(y, x, 8.3334519073e-3f);
    y = fmaf(y, x, 4.1665795894e-2f);
    y = fmaf(y, x, 1.6666665459e-1f);
    y = fmaf(y, x, 5.0000001201e-1f);
    y = fmaf(y, z, x);
    y = __fadd_rn(y, 1.0f);
    int n = (int)fx;
    float p2n = __int_as_float((n + 127) << 23);
    return __fmul_rn(y, p2n);
}
__device__ __forceinline__ float xla_sigmoid(float x) {
    float e = xla_cpu_expf(-x);
    return __fdiv_rn(1.0f, __fadd_rn(1.0f, e));
}

// ---------------- kernel 0: zero hist / counters / rowany ----------------
__global__ void init_kernel() {
    int i = blockIdx.x * blockDim.x + threadIdx.x;
    if (i < NB * NBUCK) d_hist[i] = 0;
    if (i < NB)         d_cnt[i]  = 0;
    if (i < NB * 32)    d_rowany[i] = 0;
}

// ---------------- kernel 1: scores, classes, boxes, histogram ----------------
__global__ void score_kernel(Ptrs P) {
    __shared__ int shist[NBUCK];
    int b = blockIdx.y;
    for (int i = threadIdx.x; i < NBUCK; i += blockDim.x) shist[i] = 0;
    __syncthreads();

    int a = blockIdx.x * blockDim.x + threadIdx.x;
    if (a < NANCH) {
        int lvl, off, hw, W, stride;
        if      (a < 12800) { lvl = 0; off = 0;     hw = 12800; W = 128; stride = 8;   }
        else if (a < 16000) { lvl = 1; off = 12800; hw = 3200;  W = 64;  stride = 16;  }
        else if (a < 16800) { lvl = 2; off = 16000; hw = 800;   W = 32;  stride = 32;  }
        else if (a < 17008) { lvl = 3; off = 16800; hw = 208;   W = 16;  stride = 64;  }
        else                { lvl = 4; off = 17008; hw = 56;    W = 8;   stride = 128; }
        int pix = a - off;
        int y = pix / W;
        int x = pix - y * W;
        float cx = (float)(x * stride + stride / 2);
        float cy = (float)(y * stride + stride / 2);

        const float* cp = P.cls[lvl] + (size_t)b * NCLS * hw + pix;

        // pass 1: max logit (first index) + runner-up, compares only
        float m = -3.0e38f, m2 = -3.0e38f;
        int cm = 0;
        #pragma unroll 8
        for (int c = 0; c < NCLS; c++) {
            float l = cp[(size_t)c * hw];
            if (l > m) { m2 = m; m = l; cm = c; }
            else       { m2 = fmaxf(m2, l); }
        }
        float best; int bi;
        if (m2 < __fsub_rn(m, 1.0e-3f)) {
            // unique max: sigmoid monotone over >1e-3 gaps (|logit|<=~6) => argmax/max carry over
            best = xla_sigmoid(m);
            bi = cm;
        } else {
            // rare near-tie: replicate reference scan over window candidates, in order
            best = -1.0f; bi = 0;
            float thr = __fsub_rn(m, 1.0e-3f);
            for (int c = 0; c < NCLS; c++) {
                float l = cp[(size_t)c * hw];
                if (l >= thr) {
                    float s = xla_sigmoid(l);
                    if (s > best) { best = s; bi = c; }
                }
            }
        }
        float ctr = xla_sigmoid(P.ctr[lvl][(size_t)b * hw + pix]);
        float sc  = __fmul_rn(best, ctr);

        const float* rp = P.reg[lvl] + (size_t)b * 4 * hw + pix;
        float r0 = rp[0];
        float r1 = rp[(size_t)hw];
        float r2 = rp[(size_t)2 * hw];
        float r3 = rp[(size_t)3 * hw];
        float4 bx;
        bx.x = __fsub_rn(cx, r0);
        bx.y = __fsub_rn(cy, r1);
        bx.z = __fadd_rn(cx, r2);
        bx.w = __fadd_rn(cy, r3);

        int idx = b * NANCH + a;
        d_score[idx] = sc;
        d_cls[idx]   = bi + 1;
        d_box[idx]   = bx;

        int bu = (int)(sc * 2048.0f);
        bu = bu < 0 ? 0 : (bu > 2047 ? 2047 : bu);
        atomicAdd(&shist[bu], 1);
    }
    __syncthreads();
    for (int i = threadIdx.x; i < NBUCK; i += blockDim.x) {
        int v = shist[i];
        if (v) atomicAdd(&d_hist[b * NBUCK + i], v);
    }
}

// ---------------- kernel 2: find cutoff bucket (rank-1000) ----------------
__global__ void cutoff_kernel() {
    int b = blockIdx.x;
    __shared__ int sbins[NBUCK];
    __shared__ int csum[64];
    int t = threadIdx.x;   // block = 64
    for (int k = 0; k < 32; k++) {          // coalesced copy
        int idx = t + k * 64;
        sbins[idx] = d_hist[b * NBUCK + idx];
    }
    __syncthreads();
    int s = 0;
    for (int k = 0; k < 32; k++) s += sbins[2047 - (t * 32 + k)];
    csum[t] = s;
    __syncthreads();
    if (t == 0) {
        int cum = 0, cut = 0;
        for (int ch = 0; ch < 64; ch++) {
            if (cum + csum[ch] >= TOPK) {
                for (int k = 0; k < 32; k++) {
                    int bin = 2047 - (ch * 32 + k);
                    cum += sbins[bin];
                    if (cum >= TOPK) { cut = bin; break; }
                }
                break;
            }
            cum += csum[ch];
        }
        d_cut[b] = cut;
    }
}

// ---------------- kernel 3: compact candidates ----------------
__global__ void compact_kernel() {
    int b = blockIdx.y;
    int a = blockIdx.x * blockDim.x + threadIdx.x;
    if (a >= NANCH) return;
    float sc = d_score[b * NANCH + a];
    int bu = (int)(sc * 2048.0f);
    bu = bu < 0 ? 0 : (bu > 2047 ? 2047 : bu);
    if (bu >= d_cut[b]) {
        int pos = atomicAdd(&d_cnt[b], 1);
        if (pos < CANDCAP) {
            unsigned long long key =
                ((unsigned long long)__float_as_uint(sc) << 32) |
                (unsigned)(~(unsigned)a);
            d_cand[b * CANDCAP + pos] = key;
        }
    }
}

// ---------------- kernel 4: sort + gather + M1 + offset boxes/areas ----------------
__global__ void sort_kernel() {
    __shared__ unsigned long long keys[CANDCAP];
    __shared__ float smax[33];
    int b = blockIdx.x;
    int tid = threadIdx.x;  // block = 1024
    int lane = tid & 31;
    int w = tid >> 5;
    int cnt = d_cnt[b];
    if (cnt > CANDCAP) cnt = CANDCAP;
    int n = (cnt <= 2048) ? 2048 : CANDCAP;   // uniform per block

    for (int i = tid; i < n; i += 1024)
        keys[i] = (i < cnt) ? d_cand[b * CANDCAP + i] : 0ULL;
    __syncthreads();

    for (int k = 2; k <= n; k <<= 1) {
        for (int j = k >> 1; j > 0; j >>= 1) {
            for (int i = tid; i < n; i += 1024) {
                int ixj = i ^ j;
                if (ixj > i) {
                    unsigned long long A = keys[i], Bk = keys[ixj];
                    bool desc = ((i & k) == 0);
                    bool sw = desc ? (A < Bk) : (A > Bk);
                    if (sw) { keys[i] = Bk; keys[ixj] = A; }
                }
            }
            __syncthreads();
        }
    }

    float sc = 0.0f; int cls = 0; float4 bx = make_float4(0.f, 0.f, 0.f, 0.f);
    float mloc = -3.0e38f;
    if (tid < TOPK) {
        unsigned long long key = keys[tid];
        sc = __uint_as_float((unsigned)(key >> 32));
        int a = (int)(~(unsigned)(key & 0xFFFFFFFFu));
        int src = b * NANCH + a;
        cls = d_cls[src];
        bx  = d_box[src];
        int dst = b * TOPK + tid;
        d_tscore[dst] = sc;
        d_tcls[dst]   = cls;
        d_tbox[dst]   = bx;
        mloc = fmaxf(fmaxf(bx.x, bx.y), fmaxf(bx.z, bx.w));
    }
    // block max reduction
    for (int o = 16; o; o >>= 1) mloc = fmaxf(mloc, __shfl_xor_sync(0xffffffffu, mloc, o));
    if (lane == 0) smax[w] = mloc;
    __syncthreads();
    if (w == 0) {
        float mm = smax[lane];
        for (int o = 16; o; o >>= 1) mm = fmaxf(mm, __shfl_xor_sync(0xffffffffu, mm, o));
        if (lane == 0) smax[32] = mm;
    }
    __syncthreads();
    float M1 = __fadd_rn(smax[32], 1.0f);

    if (tid < TOPK) {
        float off = __fmul_rn((float)cls, M1);
        float4 nb;
        nb.x = __fadd_rn(bx.x, off);
        nb.y = __fadd_rn(bx.y, off);
        nb.z = __fadd_rn(bx.z, off);
        nb.w = __fadd_rn(bx.w, off);
        int dst = b * TOPK + tid;
        d_nbox[dst]  = nb;
        d_narea[dst] = __fmul_rn(__fadd_rn(__fsub_rn(nb.z, nb.x), 1.0f),
                                 __fadd_rn(__fsub_rn(nb.w, nb.y), 1.0f));
    }
}

// ---------------- kernel 5: NMS suppression bitmask (spread over 8 blocks/batch) ----------------
__global__ void mask_kernel() {
    __shared__ float4 sbox[TOPK];
    __shared__ float  sarea[TOPK];
    int b = blockIdx.y;
    int tid = threadIdx.x;   // 1024
    int lane = tid & 31;
    int w = tid >> 5;
    for (int i = tid; i < TOPK; i += 1024) {
        sbox[i]  = d_nbox[b * TOPK + i];
        sarea[i] = d_narea[b * TOPK + i];
    }
    __syncthreads();

    int gw = blockIdx.x * 32 + w;   // 0..255 global warp within batch
    for (int i = gw; i < TOPK; i += 256) {
        float4 bi = sbox[i];
        double ai = (double)sarea[i];
        unsigned any = 0;
        #pragma unroll 4
        for (int wd = 0; wd < 32; wd++) {
            int j = wd * 32 + lane;
            bool pred = false;
            if (j < TOPK && j > i) {
                float4 bj = sbox[j];
                float xmin = fmaxf(bi.x, bj.x);
                float ymin = fmaxf(bi.y, bj.y);
                float xmax = fminf(bi.z, bj.z);
                float ymax = fminf(bi.w, bj.w);
                float iw = fmaxf(__fsub_rn(xmax, xmin), 0.0f);
                float ih = fmaxf(__fsub_rn(ymax, ymin), 0.0f);
                float inter = __fmul_rn(iw, ih);
                float den = __fsub_rn(__fadd_rn((float)ai, sarea[j]), inter);
                // exact replication of __fdiv_rn(inter,den) > 0.6f (den>0 here)
                pred = (double)inter > IOU_MID * (double)den;
            }
            unsigned bal = __ballot_sync(0xffffffffu, pred);
            if (lane == 0) d_mask[(b * TOPK + i) * 32 + wd] = bal;
            any |= bal;
        }
        if (lane == 0 && any) atomicOr(&d_rowany[b * 32 + (i >> 5)], 1u << (i & 31));
    }
}

// ---------------- kernel 6: greedy sweep + outputs ----------------
__global__ void sweep_kernel(float* __restrict__ out) {
    extern __shared__ char smem_raw[];
    unsigned* mask   = (unsigned*)(smem_raw);                 // 128000 B
    float*    sscore = (float*)(smem_raw + 128000);           //   4000 B
    int*      scls   = (int*)(smem_raw + 132000);             //   4000 B
    unsigned* rowAny = (unsigned*)(smem_raw + 136000);        //    128 B
    unsigned* remw   = (unsigned*)(smem_raw + 136128);        //    128 B

    int b = blockIdx.x;
    int tid = threadIdx.x;           // 1024
    int lane = tid & 31;
    int w = tid >> 5;

    for (int i = tid; i < TOPK * 32; i += 1024) mask[i] = d_mask[b * TOPK * 32 + i];
    for (int i = tid; i < TOPK; i += 1024) {
        sscore[i] = d_tscore[b * TOPK + i];
        scls[i]   = d_tcls[b * TOPK + i];
    }
    if (tid < 32) rowAny[tid] = d_rowany[b * 32 + tid];
    {
        bool invalid = (tid >= TOPK) || (d_tscore[b * TOPK + (tid < TOPK ? tid : 0)] < 0.05f) && (tid < TOPK);
        // recompute cleanly below after smem ready
        (void)invalid;
    }
    __syncthreads();

    {
        bool invalid = (tid >= TOPK) || (sscore[tid] < 0.05f);
        unsigned bal = __ballot_sync(0xffffffffu, invalid);
        if (lane == 0) remw[w] = bal;
    }
    __syncthreads();

    if (w == 0) {
        unsigned rem = remw[lane];
        for (int c = 0; c < 32; c++) {
            unsigned bits = rowAny[c];
            while (bits) {
                int bpos = __ffs(bits) - 1;
                bits &= bits - 1;
                int i = c * 32 + bpos;
                unsigned wi = __shfl_sync(0xffffffffu, rem, c);
                if (!((wi >> bpos) & 1u)) rem |= mask[i * 32 + lane];
            }
        }
        remw[lane] = rem;
    }
    __syncthreads();

    float* out_sc = out;
    float* out_cl = out + NB * TOPK;
    float* out_bx = out + 2 * NB * TOPK;
    for (int i = tid; i < TOPK; i += 1024) {
        bool kp = !((remw[i >> 5] >> (i & 31)) & 1u);
        out_sc[b * TOPK + i] = kp ? sscore[i] : 0.0f;
        out_cl[b * TOPK + i] = kp ? (float)scls[i] : 0.0f;
        float4 ob = d_tbox[b * TOPK + i];
        float4 r;
        r.x = kp ? ob.x : 0.0f;
        r.y = kp ? ob.y : 0.0f;
        r.z = kp ? ob.z : 0.0f;
        r.w = kp ? ob.w : 0.0f;
        ((float4*)out_bx)[b * TOPK + i] = r;
    }
}

// ---------------- host ----------------
extern "C" void kernel_launch(void* const* d_in, const int* in_sizes, int n_in,
                              void* d_out, int out_size) {
    Ptrs P;
    if (n_in >= 15 && in_sizes[1] == 4096000) {
        for (int i = 0; i < 5; i++) {
            P.cls[i] = (const float*)d_in[i];
            P.ctr[i] = (const float*)d_in[5 + i];
            P.reg[i] = (const float*)d_in[10 + i];
        }
    } else {
        for (int i = 0; i < 5; i++) {
            P.cls[i] = (const float*)d_in[3 * i];
            P.ctr[i] = (const float*)d_in[3 * i + 1];
            P.reg[i] = (const float*)d_in[3 * i + 2];
        }
    }

    static bool attr_set = false;
    if (!attr_set) {
        cudaFuncSetAttribute(sweep_kernel, cudaFuncAttributeMaxDynamicSharedMemorySize, 136320);
        attr_set = true;
    }

    init_kernel<<<(NB * NBUCK + 255) / 256, 256>>>();
    dim3 g2((NANCH + 255) / 256, NB);
    score_kernel<<<g2, 256>>>(P);
    cutoff_kernel<<<NB, 64>>>();
    compact_kernel<<<g2, 256>>>();
    sort_kernel<<<NB, 1024>>>();
    mask_kernel<<<dim3(8, NB), 1024>>>();
    sweep_kernel<<<NB, 1024, 136320>>>((float*)d_out);
}